// round 1
// baseline (speedup 1.0000x reference)
#include <cuda_runtime.h>
#include <math.h>

#define IN_FEATS 256
#define HIDDEN   128
#define OUT_FEATS 64
#define MAX_NODES 50048

// ---------------- scratch (static device globals; no allocation allowed) ---
__device__ float g_deg_out[MAX_NODES];
__device__ float g_deg_in[MAX_NODES];
__device__ float g_ns[MAX_NODES];
__device__ float g_nd[MAX_NODES];
__device__ float g_m1[(size_t)MAX_NODES * HIDDEN];
__device__ float g_agg1[(size_t)MAX_NODES * HIDDEN];
__device__ float g_h[(size_t)MAX_NODES * HIDDEN];
__device__ float g_m2[(size_t)MAX_NODES * OUT_FEATS];
__device__ int   g_is64;

// ---------------- index dtype detector ------------------------------------
// int64 little-endian: high word of each element is 0 (indices < 2^31, >=0).
// int32: odd words are other index values (P(all 32 zero) ~ 0).
__global__ void detect_i64_kernel(const unsigned int* __restrict__ words, int E) {
    int is64 = 1;
    int nchk = E < 32 ? E : 32;
    for (int i = 0; i < nchk; i++) {
        if (words[2 * i + 1] != 0u) { is64 = 0; break; }
    }
    g_is64 = is64;
}

__device__ __forceinline__ long long load_idx(const void* p, int i) {
    if (g_is64) return ((const long long*)p)[i];
    return (long long)((const int*)p)[i];
}

// ---------------- degrees & norms -----------------------------------------
__global__ void degree_kernel(const void* __restrict__ src, const void* __restrict__ dst, int E) {
    int e = blockIdx.x * blockDim.x + threadIdx.x;
    if (e >= E) return;
    long long s = load_idx(src, e);
    long long d = load_idx(dst, e);
    atomicAdd(&g_deg_out[s], 1.0f);
    atomicAdd(&g_deg_in[d], 1.0f);
}

__global__ void norm_kernel(int N) {
    int i = blockIdx.x * blockDim.x + threadIdx.x;
    if (i >= N) return;
    g_ns[i] = rsqrtf(fmaxf(g_deg_out[i], 1.0f));
    g_nd[i] = rsqrtf(fmaxf(g_deg_in[i], 1.0f));
}

// ---------------- GEMM: C[M,N] = (A[M,K] * rowScale) @ B[K,N] --------------
// 64x64 tile, 256 threads, 4x4 microtile per thread, K chunks of 64.
#define BM 64
#define BN 64
#define BK 64

__global__ __launch_bounds__(256) void gemm_rs_kernel(
    const float* __restrict__ A, const float* __restrict__ B,
    float* __restrict__ C, const float* __restrict__ rowScale,
    int M, int K, int N)
{
    __shared__ float As[BM][BK + 1];
    __shared__ float Bs[BK][BN];

    int tid = threadIdx.x;
    int tx = tid & 15;        // 0..15 -> 4 cols each
    int ty = tid >> 4;        // 0..15 -> 4 rows each
    int row0 = blockIdx.x * BM;
    int col0 = blockIdx.y * BN;

    float acc[4][4] = {};

    for (int k0 = 0; k0 < K; k0 += BK) {
        // load A tile (with optional per-row scale), float4 along K
        #pragma unroll
        for (int i = tid; i < BM * (BK / 4); i += 256) {
            int r  = i >> 4;
            int kc = (i & 15) << 2;
            int gr = row0 + r;
            float4 v = make_float4(0.f, 0.f, 0.f, 0.f);
            if (gr < M) {
                v = *(const float4*)(A + (size_t)gr * K + k0 + kc);
                if (rowScale) {
                    float s = rowScale[gr];
                    v.x *= s; v.y *= s; v.z *= s; v.w *= s;
                }
            }
            As[r][kc + 0] = v.x; As[r][kc + 1] = v.y;
            As[r][kc + 2] = v.z; As[r][kc + 3] = v.w;
        }
        // load B tile, float4 along N
        #pragma unroll
        for (int i = tid; i < BK * (BN / 4); i += 256) {
            int kk = i >> 4;
            int c  = (i & 15) << 2;
            *(float4*)&Bs[kk][c] =
                *(const float4*)(B + (size_t)(k0 + kk) * N + col0 + c);
        }
        __syncthreads();

        #pragma unroll 16
        for (int kk = 0; kk < BK; kk++) {
            float a0 = As[ty * 4 + 0][kk];
            float a1 = As[ty * 4 + 1][kk];
            float a2 = As[ty * 4 + 2][kk];
            float a3 = As[ty * 4 + 3][kk];
            float4 b = *(const float4*)&Bs[kk][tx * 4];
            acc[0][0] += a0 * b.x; acc[0][1] += a0 * b.y; acc[0][2] += a0 * b.z; acc[0][3] += a0 * b.w;
            acc[1][0] += a1 * b.x; acc[1][1] += a1 * b.y; acc[1][2] += a1 * b.z; acc[1][3] += a1 * b.w;
            acc[2][0] += a2 * b.x; acc[2][1] += a2 * b.y; acc[2][2] += a2 * b.z; acc[2][3] += a2 * b.w;
            acc[3][0] += a3 * b.x; acc[3][1] += a3 * b.y; acc[3][2] += a3 * b.z; acc[3][3] += a3 * b.w;
        }
        __syncthreads();
    }

    #pragma unroll
    for (int i = 0; i < 4; i++) {
        int gr = row0 + ty * 4 + i;
        if (gr < M) {
            float4 v = make_float4(acc[i][0], acc[i][1], acc[i][2], acc[i][3]);
            *(float4*)(C + (size_t)gr * N + col0 + tx * 4) = v;
        }
    }
}

// ---------------- edge scatter-add (warp per edge, vector red) -------------
template <int C>
__global__ __launch_bounds__(256) void scatter_kernel(
    const float* __restrict__ m, const void* __restrict__ srcv,
    const void* __restrict__ dstv, float* __restrict__ agg, int E)
{
    int w    = (blockIdx.x * blockDim.x + threadIdx.x) >> 5;
    int lane = threadIdx.x & 31;
    if (w >= E) return;
    long long s = load_idx(srcv, w);
    long long d = load_idx(dstv, w);
    if (C == 128) {
        float4 v = *(const float4*)(m + (size_t)s * C + lane * 4);
        float* p = agg + (size_t)d * C + lane * 4;
        asm volatile("red.global.add.v4.f32 [%0], {%1, %2, %3, %4};"
                     :: "l"(p), "f"(v.x), "f"(v.y), "f"(v.z), "f"(v.w)
                     : "memory");
    } else {
        float2 v = *(const float2*)(m + (size_t)s * C + lane * 2);
        float* p = agg + (size_t)d * C + lane * 2;
        asm volatile("red.global.add.v2.f32 [%0], {%1, %2};"
                     :: "l"(p), "f"(v.x), "f"(v.y)
                     : "memory");
    }
}

// ---------------- layer-1 epilogue: h = relu(agg*nd + b1) * ns -------------
__global__ void relu_scale_kernel(const float* __restrict__ b1, int N) {
    int idx = blockIdx.x * blockDim.x + threadIdx.x;
    if (idx >= N * HIDDEN) return;
    int i = idx / HIDDEN;
    int j = idx - i * HIDDEN;
    float v = fmaxf(g_agg1[idx] * g_nd[i] + b1[j], 0.0f);
    g_h[idx] = v * g_ns[i];
}

// ---------------- layer-2 epilogue: out = out*nd + b2 ----------------------
__global__ void out_epilogue_kernel(float* __restrict__ out, const float* __restrict__ b2, int N) {
    int idx = blockIdx.x * blockDim.x + threadIdx.x;
    if (idx >= N * OUT_FEATS) return;
    int i = idx / OUT_FEATS;
    int j = idx - i * OUT_FEATS;
    out[idx] = out[idx] * g_nd[i] + b2[j];
}

// ---------------- launch ---------------------------------------------------
extern "C" void kernel_launch(void* const* d_in, const int* in_sizes, int n_in,
                              void* d_out, int out_size) {
    const float* x  = (const float*)d_in[0];
    const void*  src = d_in[1];
    const void*  dst = d_in[2];
    const float* W1 = (const float*)d_in[3];
    const float* b1 = (const float*)d_in[4];
    const float* W2 = (const float*)d_in[5];
    const float* b2 = (const float*)d_in[6];
    float* out = (float*)d_out;

    int N = in_sizes[0] / IN_FEATS;   // 50000
    int E = in_sizes[1];              // 800000

    void *p_deg_out, *p_deg_in, *p_agg1, *p_m1, *p_h, *p_m2;
    cudaGetSymbolAddress(&p_deg_out, g_deg_out);
    cudaGetSymbolAddress(&p_deg_in,  g_deg_in);
    cudaGetSymbolAddress(&p_agg1,    g_agg1);
    cudaGetSymbolAddress(&p_m1,      g_m1);
    cudaGetSymbolAddress(&p_h,       g_h);
    cudaGetSymbolAddress(&p_m2,      g_m2);
    void *p_ns;
    cudaGetSymbolAddress(&p_ns, g_ns);

    cudaMemsetAsync(p_deg_out, 0, (size_t)N * sizeof(float));
    cudaMemsetAsync(p_deg_in,  0, (size_t)N * sizeof(float));
    cudaMemsetAsync(p_agg1,    0, (size_t)N * HIDDEN * sizeof(float));
    cudaMemsetAsync(d_out,     0, (size_t)out_size * sizeof(float));

    detect_i64_kernel<<<1, 1>>>((const unsigned int*)src, E);
    degree_kernel<<<(E + 255) / 256, 256>>>(src, dst, E);
    norm_kernel<<<(N + 255) / 256, 256>>>(N);

    // layer 1: m1 = (x * ns) @ W1
    gemm_rs_kernel<<<dim3((N + BM - 1) / BM, HIDDEN / BN), 256>>>(
        x, W1, (float*)p_m1, (const float*)p_ns, N, IN_FEATS, HIDDEN);

    // agg1 = segment_sum(m1[src], dst)
    scatter_kernel<HIDDEN><<<(E * 32 + 255) / 256, 256>>>(
        (const float*)p_m1, src, dst, (float*)p_agg1, E);

    // h = relu(agg1 * nd + b1) * ns
    relu_scale_kernel<<<(N * HIDDEN + 255) / 256, 256>>>(b1, N);

    // layer 2: m2 = h @ W2   (ns already folded into h)
    gemm_rs_kernel<<<dim3((N + BM - 1) / BM, OUT_FEATS / BN), 256>>>(
        (const float*)p_h, W2, (float*)p_m2, nullptr, N, HIDDEN, OUT_FEATS);

    // out = segment_sum(m2[src], dst)
    scatter_kernel<OUT_FEATS><<<(E * 32 + 255) / 256, 256>>>(
        (const float*)p_m2, src, dst, out, E);

    // out = out * nd + b2
    out_epilogue_kernel<<<(N * OUT_FEATS + 255) / 256, 256>>>(out, b2, N);
}

// round 3
// speedup vs baseline: 1.0343x; 1.0343x over previous
#include <cuda_runtime.h>
#include <math.h>

#define IN_FEATS 256
#define HIDDEN   128
#define OUT_FEATS 64
#define MAX_NODES 50048

// ---------------- scratch (static device globals; no allocation allowed) ---
__device__ float g_deg_out[MAX_NODES];
__device__ float g_deg_in[MAX_NODES];
__device__ float g_ns[MAX_NODES];
__device__ float g_nd[MAX_NODES];
__device__ float g_m1[(size_t)MAX_NODES * HIDDEN];
__device__ float g_agg1[(size_t)MAX_NODES * HIDDEN];
__device__ float g_m2[(size_t)MAX_NODES * OUT_FEATS];
__device__ int   g_is64;

// ---------------- index dtype detector ------------------------------------
__global__ void detect_i64_kernel(const unsigned int* __restrict__ words, int E) {
    int is64 = 1;
    int nchk = E < 32 ? E : 32;
    for (int i = 0; i < nchk; i++) {
        if (words[2 * i + 1] != 0u) { is64 = 0; break; }
    }
    g_is64 = is64;
}

__device__ __forceinline__ int load_idx(const void* p, int i) {
    if (g_is64) return (int)((const long long*)p)[i];
    return ((const int*)p)[i];
}

// ---------------- degrees & norms -----------------------------------------
__global__ void degree_kernel(const void* __restrict__ src, const void* __restrict__ dst, int E) {
    int e = blockIdx.x * blockDim.x + threadIdx.x;
    if (e >= E) return;
    atomicAdd(&g_deg_out[load_idx(src, e)], 1.0f);
    atomicAdd(&g_deg_in[load_idx(dst, e)], 1.0f);
}

__global__ void norm_kernel(int N) {
    int i = blockIdx.x * blockDim.x + threadIdx.x;
    if (i >= N) return;
    g_ns[i] = rsqrtf(fmaxf(g_deg_out[i], 1.0f));
    g_nd[i] = rsqrtf(fmaxf(g_deg_in[i], 1.0f));
}

// ---------------- bias row-broadcast init: buf[i][j] = b[j] ----------------
template <int C>
__global__ void bias_init_kernel(float* __restrict__ buf, const float* __restrict__ b, int N) {
    int idx = blockIdx.x * blockDim.x + threadIdx.x;       // float4 index
    int total = N * (C / 4);
    if (idx >= total) return;
    int j4 = idx & (C / 4 - 1);
    ((float4*)buf)[idx] = ((const float4*)b)[j4];
}

// ---------------- GEMM ------------------------------------------------------
// C[M,BN] = f(A[M,K]) @ B[K,BN]; grid.x tiles M by 128; single col-block (BN==N).
// AMODE 0: a *= ns[row]          (layer 1: x * norm_src)
// AMODE 1: a = relu(a) * ns[row] (layer 2: A = agg1 = agg*nd+b1 already)
template <int BN, int TN, int AMODE>
__global__ __launch_bounds__(256) void gemm_kernel(
    const float* __restrict__ A, const float* __restrict__ B,
    float* __restrict__ C, const float* __restrict__ ns, int M, int K)
{
    constexpr int BM = 128, BK = 16, TM = 8;
    constexpr int NA = (BM * BK / 4) / 256;   // float4 A-loads per thread (2)
    constexpr int NB = (BK * BN / 4) / 256;   // float4 B-loads per thread (2 or 1)

    __shared__ float As[2][BK][BM];
    __shared__ float Bs[2][BK][BN];

    const int tid = threadIdx.x;
    const int tx = tid % (BN / TN);
    const int ty = tid / (BN / TN);
    const int row0 = blockIdx.x * BM;

    float4 aReg[NA];
    float4 bReg[NB];

    auto loadG = [&](int k0) {
        #pragma unroll
        for (int l = 0; l < NA; l++) {
            int idx = tid + l * 256;
            int m = idx >> 2, kq = idx & 3;
            int gm = row0 + m;
            float4 v = make_float4(0.f, 0.f, 0.f, 0.f);
            if (gm < M) {
                v = *(const float4*)(A + (size_t)gm * K + k0 + kq * 4);
                float s = ns[gm];
                if (AMODE == 1) {
                    v.x = fmaxf(v.x, 0.f); v.y = fmaxf(v.y, 0.f);
                    v.z = fmaxf(v.z, 0.f); v.w = fmaxf(v.w, 0.f);
                }
                v.x *= s; v.y *= s; v.z *= s; v.w *= s;
            }
            aReg[l] = v;
        }
        #pragma unroll
        for (int l = 0; l < NB; l++) {
            int idx = tid + l * 256;
            int k = idx / (BN / 4), n4 = idx % (BN / 4);
            bReg[l] = *(const float4*)(B + (size_t)(k0 + k) * BN + n4 * 4);
        }
    };
    auto storeS = [&](int buf) {
        #pragma unroll
        for (int l = 0; l < NA; l++) {
            int idx = tid + l * 256;
            int m = idx >> 2, kq = idx & 3;
            As[buf][kq * 4 + 0][m] = aReg[l].x;
            As[buf][kq * 4 + 1][m] = aReg[l].y;
            As[buf][kq * 4 + 2][m] = aReg[l].z;
            As[buf][kq * 4 + 3][m] = aReg[l].w;
        }
        #pragma unroll
        for (int l = 0; l < NB; l++) {
            int idx = tid + l * 256;
            int k = idx / (BN / 4), n4 = idx % (BN / 4);
            *(float4*)&Bs[buf][k][n4 * 4] = bReg[l];
        }
    };

    float acc[TM][TN] = {};
    const int nT = K / BK;

    loadG(0);
    storeS(0);
    __syncthreads();

    int cur = 0;
    for (int t = 0; t < nT; t++) {
        if (t + 1 < nT) loadG((t + 1) * BK);

        #pragma unroll
        for (int kk = 0; kk < BK; kk++) {
            float a[TM], b[TN];
            #pragma unroll
            for (int i = 0; i < TM / 4; i++)
                *(float4*)&a[i * 4] = *(const float4*)&As[cur][kk][ty * TM + i * 4];
            #pragma unroll
            for (int j = 0; j < TN / 4; j++)
                *(float4*)&b[j * 4] = *(const float4*)&Bs[cur][kk][tx * TN + j * 4];
            #pragma unroll
            for (int i = 0; i < TM; i++)
                #pragma unroll
                for (int j = 0; j < TN; j++)
                    acc[i][j] += a[i] * b[j];
        }

        if (t + 1 < nT) {
            storeS(cur ^ 1);
            __syncthreads();
            cur ^= 1;
        }
    }

    #pragma unroll
    for (int i = 0; i < TM; i++) {
        int gr = row0 + ty * TM + i;
        if (gr < M) {
            #pragma unroll
            for (int j = 0; j < TN / 4; j++)
                *(float4*)(C + (size_t)gr * BN + tx * TN + j * 4) =
                    *(const float4*)&acc[i][j * 4];
        }
    }
}

// ---------------- edge scatter-add (warp per edge, scaled by nd[dst]) ------
template <int C>
__global__ __launch_bounds__(256) void scatter_kernel(
    const float* __restrict__ m, const void* __restrict__ srcv,
    const void* __restrict__ dstv, float* __restrict__ agg, int E)
{
    int w    = (blockIdx.x * blockDim.x + threadIdx.x) >> 5;
    int lane = threadIdx.x & 31;
    if (w >= E) return;
    int s = load_idx(srcv, w);
    int d = load_idx(dstv, w);
    float nd = g_nd[d];
    if (C == 128) {
        float4 v = *(const float4*)(m + (size_t)s * C + lane * 4);
        v.x *= nd; v.y *= nd; v.z *= nd; v.w *= nd;
        float* p = agg + (size_t)d * C + lane * 4;
        asm volatile("red.global.add.v4.f32 [%0], {%1, %2, %3, %4};"
                     :: "l"(p), "f"(v.x), "f"(v.y), "f"(v.z), "f"(v.w)
                     : "memory");
    } else {
        float2 v = *(const float2*)(m + (size_t)s * C + lane * 2);
        v.x *= nd; v.y *= nd;
        float* p = agg + (size_t)d * C + lane * 2;
        asm volatile("red.global.add.v2.f32 [%0], {%1, %2};"
                     :: "l"(p), "f"(v.x), "f"(v.y)
                     : "memory");
    }
}

// ---------------- launch ---------------------------------------------------
extern "C" void kernel_launch(void* const* d_in, const int* in_sizes, int n_in,
                              void* d_out, int out_size) {
    const float* x  = (const float*)d_in[0];
    const void*  src = d_in[1];
    const void*  dst = d_in[2];
    const float* W1 = (const float*)d_in[3];
    const float* b1 = (const float*)d_in[4];
    const float* W2 = (const float*)d_in[5];
    const float* b2 = (const float*)d_in[6];
    float* out = (float*)d_out;

    int N = in_sizes[0] / IN_FEATS;   // 50000
    int E = in_sizes[1];              // 800000

    void *p_deg_out, *p_deg_in, *p_agg1, *p_m1, *p_m2, *p_ns;
    cudaGetSymbolAddress(&p_deg_out, g_deg_out);
    cudaGetSymbolAddress(&p_deg_in,  g_deg_in);
    cudaGetSymbolAddress(&p_agg1,    g_agg1);
    cudaGetSymbolAddress(&p_m1,      g_m1);
    cudaGetSymbolAddress(&p_m2,      g_m2);
    cudaGetSymbolAddress(&p_ns,      g_ns);

    cudaMemsetAsync(p_deg_out, 0, (size_t)N * sizeof(float));
    cudaMemsetAsync(p_deg_in,  0, (size_t)N * sizeof(float));

    detect_i64_kernel<<<1, 1>>>((const unsigned int*)src, E);
    degree_kernel<<<(E + 255) / 256, 256>>>(src, dst, E);
    norm_kernel<<<(N + 255) / 256, 256>>>(N);

    // agg1 := b1 (so scatter yields agg*nd + b1 directly)
    bias_init_kernel<HIDDEN><<<(N * HIDDEN / 4 + 255) / 256, 256>>>(
        (float*)p_agg1, b1, N);
    // out := b2
    bias_init_kernel<OUT_FEATS><<<(N * OUT_FEATS / 4 + 255) / 256, 256>>>(
        out, b2, N);

    // layer 1: m1 = (x * ns) @ W1
    gemm_kernel<HIDDEN, 8, 0><<<(N + 127) / 128, 256>>>(
        x, W1, (float*)p_m1, (const float*)p_ns, N, IN_FEATS);

    // agg1 += sum_e m1[src] * nd[dst]   -> agg1 = agg*nd + b1
    scatter_kernel<HIDDEN><<<(E * 32 + 255) / 256, 256>>>(
        (const float*)p_m1, src, dst, (float*)p_agg1, E);

    // layer 2: m2 = (relu(agg1) * ns) @ W2   (relu+ns fused into A load)
    gemm_kernel<OUT_FEATS, 4, 1><<<(N + 127) / 128, 256>>>(
        (const float*)p_agg1, W2, (float*)p_m2, (const float*)p_ns, N, HIDDEN);

    // out += sum_e m2[src] * nd[dst]    -> out = agg*nd + b2
    scatter_kernel<OUT_FEATS><<<(E * 32 + 255) / 256, 256>>>(
        (const float*)p_m2, src, dst, out, E);
}

// round 4
// speedup vs baseline: 1.4946x; 1.4451x over previous
#include <cuda_runtime.h>
#include <math.h>

#define IN_FEATS 256
#define HIDDEN   128
#define OUT_FEATS 64
#define MAX_NODES 50048
#define MAX_EDGES 800000
#define SCAN_BLK  256

// ---------------- scratch (static device globals) --------------------------
__device__ int   g_degi_out[MAX_NODES];
__device__ int   g_degi_in[MAX_NODES];
__device__ float g_ns[MAX_NODES];
__device__ float g_nd[MAX_NODES];
__device__ int   g_row_ptr[MAX_NODES];
__device__ int   g_cursor[MAX_NODES];
__device__ int   g_sorted_src[MAX_EDGES];
__device__ int   g_bsum[(MAX_NODES + SCAN_BLK - 1) / SCAN_BLK];
__device__ int   g_bpre[(MAX_NODES + SCAN_BLK - 1) / SCAN_BLK];
__device__ float g_m1[(size_t)MAX_NODES * HIDDEN];
__device__ float g_agg1[(size_t)MAX_NODES * HIDDEN];
__device__ float g_m2[(size_t)MAX_NODES * OUT_FEATS];
__device__ int   g_is64;

// ---------------- index dtype detector ------------------------------------
__global__ void detect_i64_kernel(const unsigned int* __restrict__ words, int E) {
    int is64 = 1;
    int nchk = E < 32 ? E : 32;
    for (int i = 0; i < nchk; i++) {
        if (words[2 * i + 1] != 0u) { is64 = 0; break; }
    }
    g_is64 = is64;
}

__device__ __forceinline__ int load_idx(const void* p, int i) {
    if (g_is64) return (int)((const long long*)p)[i];
    return ((const int*)p)[i];
}

// ---------------- degrees & norms -----------------------------------------
__global__ void degree_kernel(const void* __restrict__ src, const void* __restrict__ dst, int E) {
    int e = blockIdx.x * blockDim.x + threadIdx.x;
    if (e >= E) return;
    atomicAdd(&g_degi_out[load_idx(src, e)], 1);
    atomicAdd(&g_degi_in[load_idx(dst, e)], 1);
}

__global__ void norm_kernel(int N) {
    int i = blockIdx.x * blockDim.x + threadIdx.x;
    if (i >= N) return;
    g_ns[i] = rsqrtf(fmaxf((float)g_degi_out[i], 1.0f));
    g_nd[i] = rsqrtf(fmaxf((float)g_degi_in[i], 1.0f));
}

// ---------------- exclusive scan of g_degi_in -> g_row_ptr -----------------
__global__ void scan_block_sums(int N) {
    __shared__ int sm[SCAN_BLK];
    int i = blockIdx.x * SCAN_BLK + threadIdx.x;
    int v = (i < N) ? g_degi_in[i] : 0;
    sm[threadIdx.x] = v;
    __syncthreads();
    for (int s = SCAN_BLK / 2; s > 0; s >>= 1) {
        if (threadIdx.x < s) sm[threadIdx.x] += sm[threadIdx.x + s];
        __syncthreads();
    }
    if (threadIdx.x == 0) g_bsum[blockIdx.x] = sm[0];
}

__global__ void scan_partials(int nb) {
    int run = 0;
    for (int b = 0; b < nb; b++) { g_bpre[b] = run; run += g_bsum[b]; }
}

__global__ void scan_final(int N) {
    __shared__ int sm[SCAN_BLK];
    int i = blockIdx.x * SCAN_BLK + threadIdx.x;
    int v = (i < N) ? g_degi_in[i] : 0;
    sm[threadIdx.x] = v;
    __syncthreads();
    // Hillis-Steele inclusive scan
    for (int off = 1; off < SCAN_BLK; off <<= 1) {
        int t = (threadIdx.x >= off) ? sm[threadIdx.x - off] : 0;
        __syncthreads();
        sm[threadIdx.x] += t;
        __syncthreads();
    }
    if (i < N) g_row_ptr[i] = g_bpre[blockIdx.x] + sm[threadIdx.x] - v;
}

// ---------------- counting-sort fill: sorted_src bucketed by dst -----------
__global__ void fill_csr_kernel(const void* __restrict__ src, const void* __restrict__ dst, int E) {
    int e = blockIdx.x * blockDim.x + threadIdx.x;
    if (e >= E) return;
    int s = load_idx(src, e);
    int d = load_idx(dst, e);
    int pos = g_row_ptr[d] + atomicAdd(&g_cursor[d], 1);
    g_sorted_src[pos] = s;
}

// ---------------- CSR aggregation: warp per dst node -----------------------
// agg[n] = (sum_{e in bucket(n)} m[src_e]) * nd[n] + bias
template <int C>
__global__ __launch_bounds__(256) void gather_kernel(
    const float* __restrict__ m, float* __restrict__ agg,
    const float* __restrict__ bias, int N)
{
    int n    = (blockIdx.x * blockDim.x + threadIdx.x) >> 5;
    int lane = threadIdx.x & 31;
    if (n >= N) return;
    int beg = g_row_ptr[n];
    int cnt = g_degi_in[n];
    const int* __restrict__ ss = g_sorted_src + beg;

    if (C == 128) {
        float4 acc = make_float4(0.f, 0.f, 0.f, 0.f);
        int e = 0;
        for (; e + 4 <= cnt; e += 4) {
            int s0 = ss[e], s1 = ss[e + 1], s2 = ss[e + 2], s3 = ss[e + 3];
            float4 v0 = __ldg((const float4*)(m + (size_t)s0 * C) + lane);
            float4 v1 = __ldg((const float4*)(m + (size_t)s1 * C) + lane);
            float4 v2 = __ldg((const float4*)(m + (size_t)s2 * C) + lane);
            float4 v3 = __ldg((const float4*)(m + (size_t)s3 * C) + lane);
            acc.x += v0.x + v1.x + v2.x + v3.x;
            acc.y += v0.y + v1.y + v2.y + v3.y;
            acc.z += v0.z + v1.z + v2.z + v3.z;
            acc.w += v0.w + v1.w + v2.w + v3.w;
        }
        for (; e < cnt; e++) {
            float4 v = __ldg((const float4*)(m + (size_t)ss[e] * C) + lane);
            acc.x += v.x; acc.y += v.y; acc.z += v.z; acc.w += v.w;
        }
        float nd = g_nd[n];
        float4 b = ((const float4*)bias)[lane];
        acc.x = acc.x * nd + b.x; acc.y = acc.y * nd + b.y;
        acc.z = acc.z * nd + b.z; acc.w = acc.w * nd + b.w;
        ((float4*)(agg + (size_t)n * C))[lane] = acc;
    } else {
        float2 acc = make_float2(0.f, 0.f);
        int e = 0;
        for (; e + 4 <= cnt; e += 4) {
            int s0 = ss[e], s1 = ss[e + 1], s2 = ss[e + 2], s3 = ss[e + 3];
            float2 v0 = __ldg((const float2*)(m + (size_t)s0 * C) + lane);
            float2 v1 = __ldg((const float2*)(m + (size_t)s1 * C) + lane);
            float2 v2 = __ldg((const float2*)(m + (size_t)s2 * C) + lane);
            float2 v3 = __ldg((const float2*)(m + (size_t)s3 * C) + lane);
            acc.x += v0.x + v1.x + v2.x + v3.x;
            acc.y += v0.y + v1.y + v2.y + v3.y;
        }
        for (; e < cnt; e++) {
            float2 v = __ldg((const float2*)(m + (size_t)ss[e] * C) + lane);
            acc.x += v.x; acc.y += v.y;
        }
        float nd = g_nd[n];
        float2 b = ((const float2*)bias)[lane];
        acc.x = acc.x * nd + b.x; acc.y = acc.y * nd + b.y;
        ((float2*)(agg + (size_t)n * C))[lane] = acc;
    }
}

// ---------------- GEMM ------------------------------------------------------
// C[M,BN] = f(A[M,K]) @ B[K,BN]; AMODE 0: a*=ns[row]; AMODE 1: a=relu(a)*ns[row]
template <int BN, int TN, int AMODE>
__global__ __launch_bounds__(256) void gemm_kernel(
    const float* __restrict__ A, const float* __restrict__ B,
    float* __restrict__ C, const float* __restrict__ ns, int M, int K)
{
    constexpr int BM = 128, BK = 16, TM = 8;
    constexpr int NA = (BM * BK / 4) / 256;
    constexpr int NB = (BK * BN / 4) / 256;

    __shared__ float As[2][BK][BM];
    __shared__ float Bs[2][BK][BN];

    const int tid = threadIdx.x;
    const int tx = tid % (BN / TN);
    const int ty = tid / (BN / TN);
    const int row0 = blockIdx.x * BM;

    float4 aReg[NA];
    float4 bReg[NB];

    auto loadG = [&](int k0) {
        #pragma unroll
        for (int l = 0; l < NA; l++) {
            int idx = tid + l * 256;
            int m = idx >> 2, kq = idx & 3;
            int gm = row0 + m;
            float4 v = make_float4(0.f, 0.f, 0.f, 0.f);
            if (gm < M) {
                v = *(const float4*)(A + (size_t)gm * K + k0 + kq * 4);
                float s = ns[gm];
                if (AMODE == 1) {
                    v.x = fmaxf(v.x, 0.f); v.y = fmaxf(v.y, 0.f);
                    v.z = fmaxf(v.z, 0.f); v.w = fmaxf(v.w, 0.f);
                }
                v.x *= s; v.y *= s; v.z *= s; v.w *= s;
            }
            aReg[l] = v;
        }
        #pragma unroll
        for (int l = 0; l < NB; l++) {
            int idx = tid + l * 256;
            int k = idx / (BN / 4), n4 = idx % (BN / 4);
            bReg[l] = *(const float4*)(B + (size_t)(k0 + k) * BN + n4 * 4);
        }
    };
    auto storeS = [&](int buf) {
        #pragma unroll
        for (int l = 0; l < NA; l++) {
            int idx = tid + l * 256;
            int m = idx >> 2, kq = idx & 3;
            As[buf][kq * 4 + 0][m] = aReg[l].x;
            As[buf][kq * 4 + 1][m] = aReg[l].y;
            As[buf][kq * 4 + 2][m] = aReg[l].z;
            As[buf][kq * 4 + 3][m] = aReg[l].w;
        }
        #pragma unroll
        for (int l = 0; l < NB; l++) {
            int idx = tid + l * 256;
            int k = idx / (BN / 4), n4 = idx % (BN / 4);
            *(float4*)&Bs[buf][k][n4 * 4] = bReg[l];
        }
    };

    float acc[TM][TN] = {};
    const int nT = K / BK;

    loadG(0);
    storeS(0);
    __syncthreads();

    int cur = 0;
    for (int t = 0; t < nT; t++) {
        if (t + 1 < nT) loadG((t + 1) * BK);

        #pragma unroll
        for (int kk = 0; kk < BK; kk++) {
            float a[TM], b[TN];
            #pragma unroll
            for (int i = 0; i < TM / 4; i++)
                *(float4*)&a[i * 4] = *(const float4*)&As[cur][kk][ty * TM + i * 4];
            #pragma unroll
            for (int j = 0; j < TN / 4; j++)
                *(float4*)&b[j * 4] = *(const float4*)&Bs[cur][kk][tx * TN + j * 4];
            #pragma unroll
            for (int i = 0; i < TM; i++)
                #pragma unroll
                for (int j = 0; j < TN; j++)
                    acc[i][j] += a[i] * b[j];
        }

        if (t + 1 < nT) {
            storeS(cur ^ 1);
            __syncthreads();
            cur ^= 1;
        }
    }

    #pragma unroll
    for (int i = 0; i < TM; i++) {
        int gr = row0 + ty * TM + i;
        if (gr < M) {
            #pragma unroll
            for (int j = 0; j < TN / 4; j++)
                *(float4*)(C + (size_t)gr * BN + tx * TN + j * 4) =
                    *(const float4*)&acc[i][j * 4];
        }
    }
}

// ---------------- launch ---------------------------------------------------
extern "C" void kernel_launch(void* const* d_in, const int* in_sizes, int n_in,
                              void* d_out, int out_size) {
    const float* x  = (const float*)d_in[0];
    const void*  src = d_in[1];
    const void*  dst = d_in[2];
    const float* W1 = (const float*)d_in[3];
    const float* b1 = (const float*)d_in[4];
    const float* W2 = (const float*)d_in[5];
    const float* b2 = (const float*)d_in[6];
    float* out = (float*)d_out;

    int N = in_sizes[0] / IN_FEATS;   // 50000
    int E = in_sizes[1];              // 800000
    int nb = (N + SCAN_BLK - 1) / SCAN_BLK;

    void *p_dego, *p_degi, *p_cursor, *p_agg1, *p_m1, *p_m2, *p_ns;
    cudaGetSymbolAddress(&p_dego,   g_degi_out);
    cudaGetSymbolAddress(&p_degi,   g_degi_in);
    cudaGetSymbolAddress(&p_cursor, g_cursor);
    cudaGetSymbolAddress(&p_agg1,   g_agg1);
    cudaGetSymbolAddress(&p_m1,     g_m1);
    cudaGetSymbolAddress(&p_m2,     g_m2);
    cudaGetSymbolAddress(&p_ns,     g_ns);

    cudaMemsetAsync(p_dego,   0, (size_t)N * sizeof(int));
    cudaMemsetAsync(p_degi,   0, (size_t)N * sizeof(int));
    cudaMemsetAsync(p_cursor, 0, (size_t)N * sizeof(int));

    detect_i64_kernel<<<1, 1>>>((const unsigned int*)src, E);
    degree_kernel<<<(E + 255) / 256, 256>>>(src, dst, E);
    norm_kernel<<<(N + 255) / 256, 256>>>(N);

    // CSR build: exclusive scan of in-degrees, then counting-sort fill
    scan_block_sums<<<nb, SCAN_BLK>>>(N);
    scan_partials<<<1, 1>>>(nb);
    scan_final<<<nb, SCAN_BLK>>>(N);
    fill_csr_kernel<<<(E + 255) / 256, 256>>>(src, dst, E);

    // layer 1: m1 = (x * ns) @ W1
    gemm_kernel<HIDDEN, 8, 0><<<(N + 127) / 128, 256>>>(
        x, W1, (float*)p_m1, (const float*)p_ns, N, IN_FEATS);

    // agg1 = (sum_bucket m1[src]) * nd + b1   (CSR gather, plain stores)
    gather_kernel<HIDDEN><<<(N * 32 + 255) / 256, 256>>>(
        (const float*)p_m1, (float*)p_agg1, b1, N);

    // layer 2: m2 = (relu(agg1) * ns) @ W2
    gemm_kernel<OUT_FEATS, 4, 1><<<(N + 127) / 128, 256>>>(
        (const float*)p_agg1, W2, (float*)p_m2, (const float*)p_ns, N, HIDDEN);

    // out = (sum_bucket m2[src]) * nd + b2
    gather_kernel<OUT_FEATS><<<(N * 32 + 255) / 256, 256>>>(
        (const float*)p_m2, out, b2, N);
}

// round 7
// speedup vs baseline: 2.0915x; 1.3994x over previous
#include <cuda_runtime.h>
#include <cuda_bf16.h>
#include <math.h>
#include <cstdint>

#define IN_FEATS 256
#define HIDDEN   128
#define OUT_FEATS 64
#define MAX_NODES 50048
#define MAX_EDGES 800000
#define SCAN_BLK  256

// ---------------- scratch (static device globals) --------------------------
__device__ int   g_degi_out[MAX_NODES];
__device__ int   g_degi_in[MAX_NODES];
__device__ float g_ns[MAX_NODES];
__device__ float g_nd[MAX_NODES];
__device__ int   g_row_ptr[MAX_NODES];
__device__ int   g_cursor[MAX_NODES];
__device__ int   g_sorted_src[MAX_EDGES];
__device__ int   g_bsum[(MAX_NODES + SCAN_BLK - 1) / SCAN_BLK];
__device__ int   g_bpre[(MAX_NODES + SCAN_BLK - 1) / SCAN_BLK];
__device__ float g_m1[(size_t)MAX_NODES * HIDDEN];
__device__ float g_agg1[(size_t)MAX_NODES * HIDDEN];
__device__ float g_m2[(size_t)MAX_NODES * OUT_FEATS];
// W images: [N rows][K+8 cols] bf16, hi/lo split, 16B-aligned
__device__ __align__(16) __nv_bfloat16 g_w1hi[HIDDEN * (IN_FEATS + 8)];
__device__ __align__(16) __nv_bfloat16 g_w1lo[HIDDEN * (IN_FEATS + 8)];
__device__ __align__(16) __nv_bfloat16 g_w2hi[OUT_FEATS * (HIDDEN + 8)];
__device__ __align__(16) __nv_bfloat16 g_w2lo[OUT_FEATS * (HIDDEN + 8)];
__device__ int   g_is64;

// ---------------- PTX helpers ----------------------------------------------
__device__ __forceinline__ uint32_t smem_u32(const void* p) {
    uint32_t a;
    asm("{ .reg .u64 t; cvta.to.shared.u64 t, %1; cvt.u32.u64 %0, t; }" : "=r"(a) : "l"(p));
    return a;
}

#define LDM_X4(r, a) \
    asm volatile("ldmatrix.sync.aligned.m8n8.x4.shared.b16 {%0,%1,%2,%3}, [%4];" \
        : "=r"((r)[0]), "=r"((r)[1]), "=r"((r)[2]), "=r"((r)[3]) : "r"(a))

#define MMA_BF16(d, a, b) \
    asm volatile("mma.sync.aligned.m16n8k16.row.col.f32.bf16.bf16.f32 " \
        "{%0,%1,%2,%3}, {%4,%5,%6,%7}, {%8,%9}, {%0,%1,%2,%3};" \
        : "+f"((d)[0]), "+f"((d)[1]), "+f"((d)[2]), "+f"((d)[3]) \
        : "r"((a)[0]), "r"((a)[1]), "r"((a)[2]), "r"((a)[3]), \
          "r"((b)[0]), "r"((b)[1]))

// ---------------- index dtype detector ------------------------------------
__global__ void detect_i64_kernel(const unsigned int* __restrict__ words, int E) {
    int is64 = 1;
    int nchk = E < 32 ? E : 32;
    for (int i = 0; i < nchk; i++) {
        if (words[2 * i + 1] != 0u) { is64 = 0; break; }
    }
    g_is64 = is64;
}

__device__ __forceinline__ int load_idx(const void* p, int i) {
    if (g_is64) return (int)((const long long*)p)[i];
    return ((const int*)p)[i];
}

// ---------------- degrees & norms -----------------------------------------
__global__ void degree_kernel(const void* __restrict__ src, const void* __restrict__ dst, int E) {
    int e = blockIdx.x * blockDim.x + threadIdx.x;
    if (e >= E) return;
    atomicAdd(&g_degi_out[load_idx(src, e)], 1);
    atomicAdd(&g_degi_in[load_idx(dst, e)], 1);
}

__global__ void norm_kernel(int N) {
    int i = blockIdx.x * blockDim.x + threadIdx.x;
    if (i >= N) return;
    g_ns[i] = rsqrtf(fmaxf((float)g_degi_out[i], 1.0f));
    g_nd[i] = rsqrtf(fmaxf((float)g_degi_in[i], 1.0f));
}

// ---------------- exclusive scan of g_degi_in -> g_row_ptr -----------------
__global__ void scan_block_sums(int N) {
    __shared__ int sm[SCAN_BLK];
    int i = blockIdx.x * SCAN_BLK + threadIdx.x;
    int v = (i < N) ? g_degi_in[i] : 0;
    sm[threadIdx.x] = v;
    __syncthreads();
    for (int s = SCAN_BLK / 2; s > 0; s >>= 1) {
        if (threadIdx.x < s) sm[threadIdx.x] += sm[threadIdx.x + s];
        __syncthreads();
    }
    if (threadIdx.x == 0) g_bsum[blockIdx.x] = sm[0];
}

__global__ void scan_partials(int nb) {
    int run = 0;
    for (int b = 0; b < nb; b++) { g_bpre[b] = run; run += g_bsum[b]; }
}

__global__ void scan_final(int N) {
    __shared__ int sm[SCAN_BLK];
    int i = blockIdx.x * SCAN_BLK + threadIdx.x;
    int v = (i < N) ? g_degi_in[i] : 0;
    sm[threadIdx.x] = v;
    __syncthreads();
    for (int off = 1; off < SCAN_BLK; off <<= 1) {
        int t = (threadIdx.x >= off) ? sm[threadIdx.x - off] : 0;
        __syncthreads();
        sm[threadIdx.x] += t;
        __syncthreads();
    }
    if (i < N) g_row_ptr[i] = g_bpre[blockIdx.x] + sm[threadIdx.x] - v;
}

__global__ void fill_csr_kernel(const void* __restrict__ src, const void* __restrict__ dst, int E) {
    int e = blockIdx.x * blockDim.x + threadIdx.x;
    if (e >= E) return;
    int s = load_idx(src, e);
    int d = load_idx(dst, e);
    int pos = g_row_ptr[d] + atomicAdd(&g_cursor[d], 1);
    g_sorted_src[pos] = s;
}

// ---------------- W prep: split fp32 W[K,N] -> bf16 hi/lo [N][K+8] images --
template <int K, int N>
__global__ void wprep_kernel(const float* __restrict__ W,
                             __nv_bfloat16* __restrict__ hi,
                             __nv_bfloat16* __restrict__ lo) {
    int idx = blockIdx.x * blockDim.x + threadIdx.x;
    if (idx >= K * N) return;
    int n = idx / K;
    int k = idx - n * K;
    float v = W[(size_t)k * N + n];
    __nv_bfloat16 h = __float2bfloat16(v);
    __nv_bfloat16 l = __float2bfloat16(v - __bfloat162float(h));
    hi[n * (K + 8) + k] = h;
    lo[n * (K + 8) + k] = l;
}

// ---------------- tensor-core GEMM via mma.sync bf16-split -----------------
// C[M,N] = f(A[M,KTOT]) @ W ; W as bf16 hi/lo images [N][KTOT+8]
// AMODE 0: a *= ns[row];  AMODE 1: a = relu(a) * ns[row]
template <int N, int KTOT, int AMODE>
__global__ __launch_bounds__(256) void gemm_mma_kernel(
    const float* __restrict__ A,
    const __nv_bfloat16* __restrict__ Whi, const __nv_bfloat16* __restrict__ Wlo,
    float* __restrict__ C, const float* __restrict__ ns, int M)
{
    constexpr int BK = 64, BKP = BK + 8, KP = KTOT + 8;
    constexpr int TN_W = N / 2;          // 64 (N=128) or 32 (N=64)
    constexpr int NFR = TN_W / 8;        // n8 frags per warp: 8 or 4
    constexpr int WB = N * KP;           // elems per W image

    extern __shared__ __nv_bfloat16 smbuf[];
    __nv_bfloat16* Wh = smbuf;
    __nv_bfloat16* Wl = smbuf + WB;
    __nv_bfloat16* Ah = smbuf + 2 * (size_t)WB;
    __nv_bfloat16* Al = Ah + 128 * BKP;

    const int tid = threadIdx.x, lane = tid & 31, wid = tid >> 5;
    const int wm = wid & 3, wn = wid >> 2;
    const int row0 = blockIdx.x * 128;

    // copy W images into smem (flat; WB*2 bytes each, 16B-multiple)
    {
        const float4* s1 = (const float4*)Whi;
        const float4* s2 = (const float4*)Wlo;
        float4* d1 = (float4*)Wh;
        float4* d2 = (float4*)Wl;
        #pragma unroll 4
        for (int i = tid; i < WB / 8; i += 256) { d1[i] = s1[i]; d2[i] = s2[i]; }
    }

    float acc[2][NFR][4] = {};

    // ldmatrix lane->address mappings
    const int a_row = (lane & 7) + ((lane >> 3) & 1) * 8;
    const int a_col = (lane >> 4) * 8;
    const int b_row = (lane & 7) + (lane >> 4) * 8;
    const int b_col = ((lane >> 3) & 1) * 8;

    for (int c = 0; c < KTOT / BK; c++) {
        __syncthreads();
        // load + convert A chunk: 128 rows x 64 cols fp32 -> bf16 hi/lo
        #pragma unroll
        for (int l = 0; l < 8; l++) {
            int idx = tid + l * 256;
            int m = idx >> 4, k4 = idx & 15;
            int gm = row0 + m;
            float4 v = make_float4(0.f, 0.f, 0.f, 0.f);
            if (gm < M) {
                v = *(const float4*)(A + (size_t)gm * KTOT + c * BK + k4 * 4);
                float s = ns[gm];
                if (AMODE == 1) {
                    v.x = fmaxf(v.x, 0.f); v.y = fmaxf(v.y, 0.f);
                    v.z = fmaxf(v.z, 0.f); v.w = fmaxf(v.w, 0.f);
                }
                v.x *= s; v.y *= s; v.z *= s; v.w *= s;
            }
            ushort4 h4, l4;
            __nv_bfloat16 h, lo_;
            h = __float2bfloat16(v.x); h4.x = *(unsigned short*)&h;
            lo_ = __float2bfloat16(v.x - __bfloat162float(h)); l4.x = *(unsigned short*)&lo_;
            h = __float2bfloat16(v.y); h4.y = *(unsigned short*)&h;
            lo_ = __float2bfloat16(v.y - __bfloat162float(h)); l4.y = *(unsigned short*)&lo_;
            h = __float2bfloat16(v.z); h4.z = *(unsigned short*)&h;
            lo_ = __float2bfloat16(v.z - __bfloat162float(h)); l4.z = *(unsigned short*)&lo_;
            h = __float2bfloat16(v.w); h4.w = *(unsigned short*)&h;
            lo_ = __float2bfloat16(v.w - __bfloat162float(h)); l4.w = *(unsigned short*)&lo_;
            *(ushort4*)(Ah + m * BKP + k4 * 4) = h4;
            *(ushort4*)(Al + m * BKP + k4 * 4) = l4;
        }
        __syncthreads();

        #pragma unroll
        for (int k16 = 0; k16 < BK / 16; k16++) {
            int kc = k16 * 16;
            int kg = c * BK + kc;
            uint32_t ah[2][4], al[2][4];
            #pragma unroll
            for (int mi = 0; mi < 2; mi++) {
                int ar = wm * 32 + mi * 16 + a_row;
                LDM_X4(ah[mi], smem_u32(Ah + ar * BKP + kc + a_col));
                LDM_X4(al[mi], smem_u32(Al + ar * BKP + kc + a_col));
            }
            #pragma unroll
            for (int ng = 0; ng < NFR / 2; ng++) {
                int n0 = wn * TN_W + ng * 16;
                uint32_t bh[4], bl[4];
                LDM_X4(bh, smem_u32(Wh + (n0 + b_row) * KP + kg + b_col));
                LDM_X4(bl, smem_u32(Wl + (n0 + b_row) * KP + kg + b_col));
                #pragma unroll
                for (int mi = 0; mi < 2; mi++) {
                    MMA_BF16(acc[mi][2 * ng],     ah[mi], (bh + 0));
                    MMA_BF16(acc[mi][2 * ng + 1], ah[mi], (bh + 2));
                    MMA_BF16(acc[mi][2 * ng],     ah[mi], (bl + 0));
                    MMA_BF16(acc[mi][2 * ng + 1], ah[mi], (bl + 2));
                    MMA_BF16(acc[mi][2 * ng],     al[mi], (bh + 0));
                    MMA_BF16(acc[mi][2 * ng + 1], al[mi], (bh + 2));
                }
            }
        }
    }

    // epilogue: acc -> C
    #pragma unroll
    for (int mi = 0; mi < 2; mi++) {
        int r = row0 + wm * 32 + mi * 16 + (lane >> 2);
        #pragma unroll
        for (int nf = 0; nf < NFR; nf++) {
            int col = wn * TN_W + nf * 8 + (lane & 3) * 2;
            if (r < M) {
                float2 v0 = make_float2(acc[mi][nf][0], acc[mi][nf][1]);
                *(float2*)(C + (size_t)r * N + col) = v0;
            }
            if (r + 8 < M) {
                float2 v1 = make_float2(acc[mi][nf][2], acc[mi][nf][3]);
                *(float2*)(C + (size_t)(r + 8) * N + col) = v1;
            }
        }
    }
}

// ---------------- CSR aggregation: warp per dst node -----------------------
template <int C>
__global__ __launch_bounds__(256) void gather_kernel(
    const float* __restrict__ m, float* __restrict__ agg,
    const float* __restrict__ bias, int N)
{
    int n    = (blockIdx.x * blockDim.x + threadIdx.x) >> 5;
    int lane = threadIdx.x & 31;
    if (n >= N) return;
    int beg = g_row_ptr[n];
    int cnt = g_degi_in[n];
    const int* __restrict__ ss = g_sorted_src + beg;

    if (C == 128) {
        float4 acc = make_float4(0.f, 0.f, 0.f, 0.f);
        int e = 0;
        for (; e + 4 <= cnt; e += 4) {
            int s0 = ss[e], s1 = ss[e + 1], s2 = ss[e + 2], s3 = ss[e + 3];
            float4 v0 = __ldg((const float4*)(m + (size_t)s0 * C) + lane);
            float4 v1 = __ldg((const float4*)(m + (size_t)s1 * C) + lane);
            float4 v2 = __ldg((const float4*)(m + (size_t)s2 * C) + lane);
            float4 v3 = __ldg((const float4*)(m + (size_t)s3 * C) + lane);
            acc.x += v0.x + v1.x + v2.x + v3.x;
            acc.y += v0.y + v1.y + v2.y + v3.y;
            acc.z += v0.z + v1.z + v2.z + v3.z;
            acc.w += v0.w + v1.w + v2.w + v3.w;
        }
        for (; e < cnt; e++) {
            float4 v = __ldg((const float4*)(m + (size_t)ss[e] * C) + lane);
            acc.x += v.x; acc.y += v.y; acc.z += v.z; acc.w += v.w;
        }
        float nd = g_nd[n];
        float4 b = ((const float4*)bias)[lane];
        acc.x = acc.x * nd + b.x; acc.y = acc.y * nd + b.y;
        acc.z = acc.z * nd + b.z; acc.w = acc.w * nd + b.w;
        ((float4*)(agg + (size_t)n * C))[lane] = acc;
    } else {
        float2 acc = make_float2(0.f, 0.f);
        int e = 0;
        for (; e + 4 <= cnt; e += 4) {
            int s0 = ss[e], s1 = ss[e + 1], s2 = ss[e + 2], s3 = ss[e + 3];
            float2 v0 = __ldg((const float2*)(m + (size_t)s0 * C) + lane);
            float2 v1 = __ldg((const float2*)(m + (size_t)s1 * C) + lane);
            float2 v2 = __ldg((const float2*)(m + (size_t)s2 * C) + lane);
            float2 v3 = __ldg((const float2*)(m + (size_t)s3 * C) + lane);
            acc.x += v0.x + v1.x + v2.x + v3.x;
            acc.y += v0.y + v1.y + v2.y + v3.y;
        }
        for (; e < cnt; e++) {
            float2 v = __ldg((const float2*)(m + (size_t)ss[e] * C) + lane);
            acc.x += v.x; acc.y += v.y;
        }
        float nd = g_nd[n];
        float2 b = ((const float2*)bias)[lane];
        acc.x = acc.x * nd + b.x; acc.y = acc.y * nd + b.y;
        ((float2*)(agg + (size_t)n * C))[lane] = acc;
    }
}

// ---------------- launch ---------------------------------------------------
extern "C" void kernel_launch(void* const* d_in, const int* in_sizes, int n_in,
                              void* d_out, int out_size) {
    const float* x  = (const float*)d_in[0];
    const void*  src = d_in[1];
    const void*  dst = d_in[2];
    const float* W1 = (const float*)d_in[3];
    const float* b1 = (const float*)d_in[4];
    const float* W2 = (const float*)d_in[5];
    const float* b2 = (const float*)d_in[6];
    float* out = (float*)d_out;

    int N = in_sizes[0] / IN_FEATS;   // 50000
    int E = in_sizes[1];              // 800000
    int nb = (N + SCAN_BLK - 1) / SCAN_BLK;

    void *p_dego, *p_degi, *p_cursor, *p_agg1, *p_m1, *p_m2, *p_ns;
    void *p_w1hi, *p_w1lo, *p_w2hi, *p_w2lo;
    cudaGetSymbolAddress(&p_dego,   g_degi_out);
    cudaGetSymbolAddress(&p_degi,   g_degi_in);
    cudaGetSymbolAddress(&p_cursor, g_cursor);
    cudaGetSymbolAddress(&p_agg1,   g_agg1);
    cudaGetSymbolAddress(&p_m1,     g_m1);
    cudaGetSymbolAddress(&p_m2,     g_m2);
    cudaGetSymbolAddress(&p_ns,     g_ns);
    cudaGetSymbolAddress(&p_w1hi,   g_w1hi);
    cudaGetSymbolAddress(&p_w1lo,   g_w1lo);
    cudaGetSymbolAddress(&p_w2hi,   g_w2hi);
    cudaGetSymbolAddress(&p_w2lo,   g_w2lo);

    // smem: 2 W images + 2 A-chunk images
    constexpr int SMEM1 = 2 * HIDDEN * (IN_FEATS + 8) * 2 + 2 * 128 * 72 * 2;   // 172032
    constexpr int SMEM2 = 2 * OUT_FEATS * (HIDDEN + 8) * 2 + 2 * 128 * 72 * 2;  // 71680
    cudaFuncSetAttribute(gemm_mma_kernel<HIDDEN, IN_FEATS, 0>,
                         cudaFuncAttributeMaxDynamicSharedMemorySize, SMEM1);
    cudaFuncSetAttribute(gemm_mma_kernel<OUT_FEATS, HIDDEN, 1>,
                         cudaFuncAttributeMaxDynamicSharedMemorySize, SMEM2);

    cudaMemsetAsync(p_dego,   0, (size_t)N * sizeof(int));
    cudaMemsetAsync(p_degi,   0, (size_t)N * sizeof(int));
    cudaMemsetAsync(p_cursor, 0, (size_t)N * sizeof(int));

    detect_i64_kernel<<<1, 1>>>((const unsigned int*)src, E);

    wprep_kernel<IN_FEATS, HIDDEN><<<(IN_FEATS * HIDDEN + 255) / 256, 256>>>(
        W1, (__nv_bfloat16*)p_w1hi, (__nv_bfloat16*)p_w1lo);
    wprep_kernel<HIDDEN, OUT_FEATS><<<(HIDDEN * OUT_FEATS + 255) / 256, 256>>>(
        W2, (__nv_bfloat16*)p_w2hi, (__nv_bfloat16*)p_w2lo);

    degree_kernel<<<(E + 255) / 256, 256>>>(src, dst, E);
    norm_kernel<<<(N + 255) / 256, 256>>>(N);

    scan_block_sums<<<nb, SCAN_BLK>>>(N);
    scan_partials<<<1, 1>>>(nb);
    scan_final<<<nb, SCAN_BLK>>>(N);
    fill_csr_kernel<<<(E + 255) / 256, 256>>>(src, dst, E);

    // layer 1: m1 = (x * ns) @ W1  (bf16-split mma.sync)
    gemm_mma_kernel<HIDDEN, IN_FEATS, 0><<<(N + 127) / 128, 256, SMEM1>>>(
        x, (const __nv_bfloat16*)p_w1hi, (const __nv_bfloat16*)p_w1lo,
        (float*)p_m1, (const float*)p_ns, N);

    // agg1 = (sum_bucket m1[src]) * nd + b1
    gather_kernel<HIDDEN><<<(N * 32 + 255) / 256, 256>>>(
        (const float*)p_m1, (float*)p_agg1, b1, N);

    // layer 2: m2 = (relu(agg1) * ns) @ W2  (bf16-split mma.sync)
    gemm_mma_kernel<OUT_FEATS, HIDDEN, 1><<<(N + 127) / 128, 256, SMEM2>>>(
        (const float*)p_agg1, (const __nv_bfloat16*)p_w2hi, (const __nv_bfloat16*)p_w2lo,
        (float*)p_m2, (const float*)p_ns, N);

    // out = (sum_bucket m2[src]) * nd + b2
    gather_kernel<OUT_FEATS><<<(N * 32 + 255) / 256, 256>>>(
        (const float*)p_m2, out, b2, N);
}

// round 8
// speedup vs baseline: 2.3016x; 1.1005x over previous
#include <cuda_runtime.h>
#include <cuda_bf16.h>
#include <cuda_fp16.h>
#include <math.h>
#include <cstdint>

#define IN_FEATS 256
#define HIDDEN   128
#define OUT_FEATS 64
#define MAX_NODES 50048
#define MAX_EDGES 800000
#define SCAN_BLK  256

// ---------------- scratch (static device globals) --------------------------
__device__ int   g_degi_out[MAX_NODES];
__device__ int   g_degi_in[MAX_NODES];
__device__ float g_ns[MAX_NODES];
__device__ float g_nd[MAX_NODES];
__device__ int   g_row_ptr[MAX_NODES];
__device__ int   g_cursor[MAX_NODES];
__device__ int   g_sorted_src[MAX_EDGES];
__device__ int   g_bsum[(MAX_NODES + SCAN_BLK - 1) / SCAN_BLK];
__device__ int   g_bpre[(MAX_NODES + SCAN_BLK - 1) / SCAN_BLK];
__device__ __align__(16) __half g_m1[(size_t)MAX_NODES * HIDDEN];
__device__ float g_agg1[(size_t)MAX_NODES * HIDDEN];
__device__ __align__(16) __half g_m2[(size_t)MAX_NODES * OUT_FEATS];
// W images: [N rows][K+8 cols] bf16, hi/lo split, 16B-aligned
__device__ __align__(16) __nv_bfloat16 g_w1hi[HIDDEN * (IN_FEATS + 8)];
__device__ __align__(16) __nv_bfloat16 g_w1lo[HIDDEN * (IN_FEATS + 8)];
__device__ __align__(16) __nv_bfloat16 g_w2hi[OUT_FEATS * (HIDDEN + 8)];
__device__ __align__(16) __nv_bfloat16 g_w2lo[OUT_FEATS * (HIDDEN + 8)];
__device__ int   g_is64;

// ---------------- PTX helpers ----------------------------------------------
__device__ __forceinline__ uint32_t smem_u32(const void* p) {
    uint32_t a;
    asm("{ .reg .u64 t; cvta.to.shared.u64 t, %1; cvt.u32.u64 %0, t; }" : "=r"(a) : "l"(p));
    return a;
}

#define LDM_X4(r, a) \
    asm volatile("ldmatrix.sync.aligned.m8n8.x4.shared.b16 {%0,%1,%2,%3}, [%4];" \
        : "=r"((r)[0]), "=r"((r)[1]), "=r"((r)[2]), "=r"((r)[3]) : "r"(a))

#define MMA_BF16(d, a, b) \
    asm volatile("mma.sync.aligned.m16n8k16.row.col.f32.bf16.bf16.f32 " \
        "{%0,%1,%2,%3}, {%4,%5,%6,%7}, {%8,%9}, {%0,%1,%2,%3};" \
        : "+f"((d)[0]), "+f"((d)[1]), "+f"((d)[2]), "+f"((d)[3]) \
        : "r"((a)[0]), "r"((a)[1]), "r"((a)[2]), "r"((a)[3]), \
          "r"((b)[0]), "r"((b)[1]))

// ---------------- index dtype detector ------------------------------------
__global__ void detect_i64_kernel(const unsigned int* __restrict__ words, int E) {
    int is64 = 1;
    int nchk = E < 32 ? E : 32;
    for (int i = 0; i < nchk; i++) {
        if (words[2 * i + 1] != 0u) { is64 = 0; break; }
    }
    g_is64 = is64;
}

__device__ __forceinline__ int load_idx(const void* p, int i) {
    if (g_is64) return (int)((const long long*)p)[i];
    return ((const int*)p)[i];
}

// ---------------- degrees (4 edges/thread for MLP) -------------------------
__global__ void degree_kernel(const void* __restrict__ src, const void* __restrict__ dst, int E) {
    int e0 = (blockIdx.x * blockDim.x + threadIdx.x) * 4;
    int s[4], d[4];
    #pragma unroll
    for (int i = 0; i < 4; i++) {
        int e = e0 + i;
        if (e < E) { s[i] = load_idx(src, e); d[i] = load_idx(dst, e); }
        else { s[i] = -1; d[i] = -1; }
    }
    #pragma unroll
    for (int i = 0; i < 4; i++) {
        if (s[i] >= 0) {
            atomicAdd(&g_degi_out[s[i]], 1);
            atomicAdd(&g_degi_in[d[i]], 1);
        }
    }
}

// ---------------- exclusive scan of g_degi_in -> g_row_ptr -----------------
__global__ void scan_block_sums(int N) {
    __shared__ int sm[SCAN_BLK];
    int i = blockIdx.x * SCAN_BLK + threadIdx.x;
    int v = (i < N) ? g_degi_in[i] : 0;
    sm[threadIdx.x] = v;
    __syncthreads();
    for (int s = SCAN_BLK / 2; s > 0; s >>= 1) {
        if (threadIdx.x < s) sm[threadIdx.x] += sm[threadIdx.x + s];
        __syncthreads();
    }
    if (threadIdx.x == 0) g_bsum[blockIdx.x] = sm[0];
}

__global__ void scan_partials(int nb) {
    int run = 0;
    for (int b = 0; b < nb; b++) { g_bpre[b] = run; run += g_bsum[b]; }
}

// scan_final also computes norms and zeroes the cursor (fused)
__global__ void scan_final(int N) {
    __shared__ int sm[SCAN_BLK];
    int i = blockIdx.x * SCAN_BLK + threadIdx.x;
    int v = (i < N) ? g_degi_in[i] : 0;
    sm[threadIdx.x] = v;
    __syncthreads();
    for (int off = 1; off < SCAN_BLK; off <<= 1) {
        int t = (threadIdx.x >= off) ? sm[threadIdx.x - off] : 0;
        __syncthreads();
        sm[threadIdx.x] += t;
        __syncthreads();
    }
    if (i < N) {
        g_row_ptr[i] = g_bpre[blockIdx.x] + sm[threadIdx.x] - v;
        g_cursor[i] = 0;
        g_ns[i] = rsqrtf(fmaxf((float)g_degi_out[i], 1.0f));
        g_nd[i] = rsqrtf(fmaxf((float)v, 1.0f));
    }
}

// ---------------- counting-sort fill (4 edges/thread) ----------------------
__global__ void fill_csr_kernel(const void* __restrict__ src, const void* __restrict__ dst, int E) {
    int e0 = (blockIdx.x * blockDim.x + threadIdx.x) * 4;
    int s[4], d[4];
    #pragma unroll
    for (int i = 0; i < 4; i++) {
        int e = e0 + i;
        if (e < E) { s[i] = load_idx(src, e); d[i] = load_idx(dst, e); }
        else { s[i] = -1; d[i] = -1; }
    }
    #pragma unroll
    for (int i = 0; i < 4; i++) {
        if (s[i] >= 0) {
            int pos = g_row_ptr[d[i]] + atomicAdd(&g_cursor[d[i]], 1);
            g_sorted_src[pos] = s[i];
        }
    }
}

// ---------------- W prep: split fp32 W[K,N] -> bf16 hi/lo [N][K+8] images --
template <int K, int N>
__global__ void wprep_kernel(const float* __restrict__ W,
                             __nv_bfloat16* __restrict__ hi,
                             __nv_bfloat16* __restrict__ lo) {
    int idx = blockIdx.x * blockDim.x + threadIdx.x;
    if (idx >= K * N) return;
    int n = idx / K;
    int k = idx - n * K;
    float v = W[(size_t)k * N + n];
    __nv_bfloat16 h = __float2bfloat16(v);
    __nv_bfloat16 l = __float2bfloat16(v - __bfloat162float(h));
    hi[n * (K + 8) + k] = h;
    lo[n * (K + 8) + k] = l;
}

// ---------------- tensor-core GEMM via mma.sync bf16-split -----------------
// C[M,N] (fp16) = f(A[M,KTOT]) @ W ; W as bf16 hi/lo images [N][KTOT+8]
// AMODE 0: a *= ns[row];  AMODE 1: a = relu(a) * ns[row]
template <int N, int KTOT, int AMODE>
__global__ __launch_bounds__(256) void gemm_mma_kernel(
    const float* __restrict__ A,
    const __nv_bfloat16* __restrict__ Whi, const __nv_bfloat16* __restrict__ Wlo,
    __half* __restrict__ C, const float* __restrict__ ns, int M)
{
    constexpr int BK = 64, BKP = BK + 8, KP = KTOT + 8;
    constexpr int TN_W = N / 2;          // 64 (N=128) or 32 (N=64)
    constexpr int NFR = TN_W / 8;        // n8 frags per warp: 8 or 4
    constexpr int WB = N * KP;           // elems per W image

    extern __shared__ __nv_bfloat16 smbuf[];
    __nv_bfloat16* Wh = smbuf;
    __nv_bfloat16* Wl = smbuf + WB;
    __nv_bfloat16* Ah = smbuf + 2 * (size_t)WB;
    __nv_bfloat16* Al = Ah + 128 * BKP;

    const int tid = threadIdx.x, lane = tid & 31, wid = tid >> 5;
    const int wm = wid & 3, wn = wid >> 2;
    const int row0 = blockIdx.x * 128;

    // copy W images into smem
    {
        const float4* s1 = (const float4*)Whi;
        const float4* s2 = (const float4*)Wlo;
        float4* d1 = (float4*)Wh;
        float4* d2 = (float4*)Wl;
        #pragma unroll 4
        for (int i = tid; i < WB / 8; i += 256) { d1[i] = s1[i]; d2[i] = s2[i]; }
    }

    float acc[2][NFR][4] = {};

    const int a_row = (lane & 7) + ((lane >> 3) & 1) * 8;
    const int a_col = (lane >> 4) * 8;
    const int b_row = (lane & 7) + (lane >> 4) * 8;
    const int b_col = ((lane >> 3) & 1) * 8;

    for (int c = 0; c < KTOT / BK; c++) {
        __syncthreads();
        // load + convert A chunk: 128 rows x 64 cols fp32 -> bf16 hi/lo
        #pragma unroll
        for (int l = 0; l < 8; l++) {
            int idx = tid + l * 256;
            int m = idx >> 4, k4 = idx & 15;
            int gm = row0 + m;
            float4 v = make_float4(0.f, 0.f, 0.f, 0.f);
            if (gm < M) {
                v = *(const float4*)(A + (size_t)gm * KTOT + c * BK + k4 * 4);
                float s = ns[gm];
                if (AMODE == 1) {
                    v.x = fmaxf(v.x, 0.f); v.y = fmaxf(v.y, 0.f);
                    v.z = fmaxf(v.z, 0.f); v.w = fmaxf(v.w, 0.f);
                }
                v.x *= s; v.y *= s; v.z *= s; v.w *= s;
            }
            ushort4 h4, l4;
            __nv_bfloat16 h, lo_;
            h = __float2bfloat16(v.x); h4.x = *(unsigned short*)&h;
            lo_ = __float2bfloat16(v.x - __bfloat162float(h)); l4.x = *(unsigned short*)&lo_;
            h = __float2bfloat16(v.y); h4.y = *(unsigned short*)&h;
            lo_ = __float2bfloat16(v.y - __bfloat162float(h)); l4.y = *(unsigned short*)&lo_;
            h = __float2bfloat16(v.z); h4.z = *(unsigned short*)&h;
            lo_ = __float2bfloat16(v.z - __bfloat162float(h)); l4.z = *(unsigned short*)&lo_;
            h = __float2bfloat16(v.w); h4.w = *(unsigned short*)&h;
            lo_ = __float2bfloat16(v.w - __bfloat162float(h)); l4.w = *(unsigned short*)&lo_;
            *(ushort4*)(Ah + m * BKP + k4 * 4) = h4;
            *(ushort4*)(Al + m * BKP + k4 * 4) = l4;
        }
        __syncthreads();

        #pragma unroll
        for (int k16 = 0; k16 < BK / 16; k16++) {
            int kc = k16 * 16;
            int kg = c * BK + kc;
            uint32_t ah[2][4], al[2][4];
            #pragma unroll
            for (int mi = 0; mi < 2; mi++) {
                int ar = wm * 32 + mi * 16 + a_row;
                LDM_X4(ah[mi], smem_u32(Ah + ar * BKP + kc + a_col));
                LDM_X4(al[mi], smem_u32(Al + ar * BKP + kc + a_col));
            }
            #pragma unroll
            for (int ng = 0; ng < NFR / 2; ng++) {
                int n0 = wn * TN_W + ng * 16;
                uint32_t bh[4], bl[4];
                LDM_X4(bh, smem_u32(Wh + (n0 + b_row) * KP + kg + b_col));
                LDM_X4(bl, smem_u32(Wl + (n0 + b_row) * KP + kg + b_col));
                #pragma unroll
                for (int mi = 0; mi < 2; mi++) {
                    MMA_BF16(acc[mi][2 * ng],     ah[mi], (bh + 0));
                    MMA_BF16(acc[mi][2 * ng + 1], ah[mi], (bh + 2));
                    MMA_BF16(acc[mi][2 * ng],     ah[mi], (bl + 0));
                    MMA_BF16(acc[mi][2 * ng + 1], ah[mi], (bl + 2));
                    MMA_BF16(acc[mi][2 * ng],     al[mi], (bh + 0));
                    MMA_BF16(acc[mi][2 * ng + 1], al[mi], (bh + 2));
                }
            }
        }
    }

    // epilogue: acc -> C (fp16)
    #pragma unroll
    for (int mi = 0; mi < 2; mi++) {
        int r = row0 + wm * 32 + mi * 16 + (lane >> 2);
        #pragma unroll
        for (int nf = 0; nf < NFR; nf++) {
            int col = wn * TN_W + nf * 8 + (lane & 3) * 2;
            if (r < M)
                *(__half2*)(C + (size_t)r * N + col) =
                    __floats2half2_rn(acc[mi][nf][0], acc[mi][nf][1]);
            if (r + 8 < M)
                *(__half2*)(C + (size_t)(r + 8) * N + col) =
                    __floats2half2_rn(acc[mi][nf][2], acc[mi][nf][3]);
        }
    }
}

// ---------------- CSR aggregation (fp16 messages): warp per dst node -------
// agg[n] = (sum_bucket m[src]) * nd[n] + bias   (fp32 accumulate/output)
template <int C>
__global__ __launch_bounds__(256) void gather_kernel(
    const __half* __restrict__ m, float* __restrict__ agg,
    const float* __restrict__ bias, int N)
{
    int n    = (blockIdx.x * blockDim.x + threadIdx.x) >> 5;
    int lane = threadIdx.x & 31;
    if (n >= N) return;
    int beg = g_row_ptr[n];
    int cnt = g_degi_in[n];
    const int* __restrict__ ss = g_sorted_src + beg;

    if (C == 128) {
        // lane covers 4 halfs = 1 uint2 (8B) per row
        float4 acc = make_float4(0.f, 0.f, 0.f, 0.f);
        int e = 0;
        for (; e + 4 <= cnt; e += 4) {
            int s0 = ss[e], s1 = ss[e + 1], s2 = ss[e + 2], s3 = ss[e + 3];
            uint2 r0 = __ldg((const uint2*)(m + (size_t)s0 * C) + lane);
            uint2 r1 = __ldg((const uint2*)(m + (size_t)s1 * C) + lane);
            uint2 r2 = __ldg((const uint2*)(m + (size_t)s2 * C) + lane);
            uint2 r3 = __ldg((const uint2*)(m + (size_t)s3 * C) + lane);
            float2 a, b;
            a = __half22float2(*(__half2*)&r0.x); b = __half22float2(*(__half2*)&r0.y);
            acc.x += a.x; acc.y += a.y; acc.z += b.x; acc.w += b.y;
            a = __half22float2(*(__half2*)&r1.x); b = __half22float2(*(__half2*)&r1.y);
            acc.x += a.x; acc.y += a.y; acc.z += b.x; acc.w += b.y;
            a = __half22float2(*(__half2*)&r2.x); b = __half22float2(*(__half2*)&r2.y);
            acc.x += a.x; acc.y += a.y; acc.z += b.x; acc.w += b.y;
            a = __half22float2(*(__half2*)&r3.x); b = __half22float2(*(__half2*)&r3.y);
            acc.x += a.x; acc.y += a.y; acc.z += b.x; acc.w += b.y;
        }
        for (; e < cnt; e++) {
            uint2 r0 = __ldg((const uint2*)(m + (size_t)ss[e] * C) + lane);
            float2 a = __half22float2(*(__half2*)&r0.x);
            float2 b = __half22float2(*(__half2*)&r0.y);
            acc.x += a.x; acc.y += a.y; acc.z += b.x; acc.w += b.y;
        }
        float nd = g_nd[n];
        float4 bb = ((const float4*)bias)[lane];
        acc.x = acc.x * nd + bb.x; acc.y = acc.y * nd + bb.y;
        acc.z = acc.z * nd + bb.z; acc.w = acc.w * nd + bb.w;
        ((float4*)(agg + (size_t)n * C))[lane] = acc;
    } else {
        // C==64: lane covers 2 halfs = 1 half2 (4B) per row
        float2 acc = make_float2(0.f, 0.f);
        int e = 0;
        for (; e + 4 <= cnt; e += 4) {
            int s0 = ss[e], s1 = ss[e + 1], s2 = ss[e + 2], s3 = ss[e + 3];
            uint32_t r0 = __ldg((const uint32_t*)(m + (size_t)s0 * C) + lane);
            uint32_t r1 = __ldg((const uint32_t*)(m + (size_t)s1 * C) + lane);
            uint32_t r2 = __ldg((const uint32_t*)(m + (size_t)s2 * C) + lane);
            uint32_t r3 = __ldg((const uint32_t*)(m + (size_t)s3 * C) + lane);
            float2 a;
            a = __half22float2(*(__half2*)&r0); acc.x += a.x; acc.y += a.y;
            a = __half22float2(*(__half2*)&r1); acc.x += a.x; acc.y += a.y;
            a = __half22float2(*(__half2*)&r2); acc.x += a.x; acc.y += a.y;
            a = __half22float2(*(__half2*)&r3); acc.x += a.x; acc.y += a.y;
        }
        for (; e < cnt; e++) {
            uint32_t r0 = __ldg((const uint32_t*)(m + (size_t)ss[e] * C) + lane);
            float2 a = __half22float2(*(__half2*)&r0);
            acc.x += a.x; acc.y += a.y;
        }
        float nd = g_nd[n];
        float2 bb = ((const float2*)bias)[lane];
        acc.x = acc.x * nd + bb.x; acc.y = acc.y * nd + bb.y;
        ((float2*)(agg + (size_t)n * C))[lane] = acc;
    }
}

// ---------------- launch ---------------------------------------------------
extern "C" void kernel_launch(void* const* d_in, const int* in_sizes, int n_in,
                              void* d_out, int out_size) {
    const float* x  = (const float*)d_in[0];
    const void*  src = d_in[1];
    const void*  dst = d_in[2];
    const float* W1 = (const float*)d_in[3];
    const float* b1 = (const float*)d_in[4];
    const float* W2 = (const float*)d_in[5];
    const float* b2 = (const float*)d_in[6];
    float* out = (float*)d_out;

    int N = in_sizes[0] / IN_FEATS;   // 50000
    int E = in_sizes[1];              // 800000
    int nb = (N + SCAN_BLK - 1) / SCAN_BLK;

    void *p_dego, *p_degi, *p_agg1, *p_m1, *p_m2, *p_ns;
    void *p_w1hi, *p_w1lo, *p_w2hi, *p_w2lo;
    cudaGetSymbolAddress(&p_dego,   g_degi_out);
    cudaGetSymbolAddress(&p_degi,   g_degi_in);
    cudaGetSymbolAddress(&p_agg1,   g_agg1);
    cudaGetSymbolAddress(&p_m1,     g_m1);
    cudaGetSymbolAddress(&p_m2,     g_m2);
    cudaGetSymbolAddress(&p_ns,     g_ns);
    cudaGetSymbolAddress(&p_w1hi,   g_w1hi);
    cudaGetSymbolAddress(&p_w1lo,   g_w1lo);
    cudaGetSymbolAddress(&p_w2hi,   g_w2hi);
    cudaGetSymbolAddress(&p_w2lo,   g_w2lo);

    constexpr int SMEM1 = 2 * HIDDEN * (IN_FEATS + 8) * 2 + 2 * 128 * 72 * 2;   // 172032
    constexpr int SMEM2 = 2 * OUT_FEATS * (HIDDEN + 8) * 2 + 2 * 128 * 72 * 2;  // 71680
    cudaFuncSetAttribute(gemm_mma_kernel<HIDDEN, IN_FEATS, 0>,
                         cudaFuncAttributeMaxDynamicSharedMemorySize, SMEM1);
    cudaFuncSetAttribute(gemm_mma_kernel<OUT_FEATS, HIDDEN, 1>,
                         cudaFuncAttributeMaxDynamicSharedMemorySize, SMEM2);

    cudaMemsetAsync(p_dego, 0, (size_t)N * sizeof(int));
    cudaMemsetAsync(p_degi, 0, (size_t)N * sizeof(int));

    detect_i64_kernel<<<1, 1>>>((const unsigned int*)src, E);

    wprep_kernel<IN_FEATS, HIDDEN><<<(IN_FEATS * HIDDEN + 255) / 256, 256>>>(
        W1, (__nv_bfloat16*)p_w1hi, (__nv_bfloat16*)p_w1lo);
    wprep_kernel<HIDDEN, OUT_FEATS><<<(HIDDEN * OUT_FEATS + 255) / 256, 256>>>(
        W2, (__nv_bfloat16*)p_w2hi, (__nv_bfloat16*)p_w2lo);

    degree_kernel<<<(E / 4 + 255) / 256, 256>>>(src, dst, E);

    scan_block_sums<<<nb, SCAN_BLK>>>(N);
    scan_partials<<<1, 1>>>(nb);
    scan_final<<<nb, SCAN_BLK>>>(N);          // row_ptr + norms + cursor=0
    fill_csr_kernel<<<(E / 4 + 255) / 256, 256>>>(src, dst, E);

    // layer 1: m1 = (x * ns) @ W1  -> fp16
    gemm_mma_kernel<HIDDEN, IN_FEATS, 0><<<(N + 127) / 128, 256, SMEM1>>>(
        x, (const __nv_bfloat16*)p_w1hi, (const __nv_bfloat16*)p_w1lo,
        (__half*)p_m1, (const float*)p_ns, N);

    // agg1 = (sum_bucket m1[src]) * nd + b1  (fp32)
    gather_kernel<HIDDEN><<<(N * 32 + 255) / 256, 256>>>(
        (const __half*)p_m1, (float*)p_agg1, b1, N);

    // layer 2: m2 = (relu(agg1) * ns) @ W2  -> fp16
    gemm_mma_kernel<OUT_FEATS, HIDDEN, 1><<<(N + 127) / 128, 256, SMEM2>>>(
        (const float*)p_agg1, (const __nv_bfloat16*)p_w2hi, (const __nv_bfloat16*)p_w2lo,
        (__half*)p_m2, (const float*)p_ns, N);

    // out = (sum_bucket m2[src]) * nd + b2  (fp32)
    gather_kernel<OUT_FEATS><<<(N * 32 + 255) / 256, 256>>>(
        (const __half*)p_m2, out, b2, N);
}